// round 12
// baseline (speedup 1.0000x reference)
#include <cuda_runtime.h>
#include <cuda_fp16.h>
#include <cstdint>

// ---------------------------------------------------------------------------
// Decoder step: B=256, T=1, I=256, H=512, A=400, V=50000, OOV=50
// out: (256, 50050) float32
//
// ISA CEILING (learned R6): harness compiles at compute_103 (no 'a' suffix).
// tcgen05.*, TMA tensor ops are REJECTED by ptxas. Allowed: mma.sync (sm_80),
// ldmatrix, cp.async, mbarrier. Do not retry tcgen05.
//
// R10: identical compute to R9 (fp16 m16n8k16 + ldmatrix, passed @358us);
// single change: fc2_w fp32->fp16 convert (~205MB read) forked onto a side
// stream, overlapped with the gates->lstm->e->attn->fc1 chain, joined via
// event before the fc2 GEMM. Streams/events created once on the first
// (uncaptured) call; capture sees only launches + event edges.
// ---------------------------------------------------------------------------

#define BATCH 256
#define IDIM  256
#define HDIM  512
#define ADIM  400
#define VDIM  50000
#define OUTC  50050

// ---------------- scratch (__device__ globals, no allocs allowed) ----------
__device__ __align__(16) __half g_fc2w_h[(size_t)VDIM * 1024];  // 100 MB
__device__ __align__(16) __half g_wih_h[2048 * IDIM];
__device__ __align__(16) __half g_catw_h[ADIM * 1024];
__device__ __align__(16) __half g_fc1w_h[1024 * 912];
__device__ __align__(16) __half g_x_h[BATCH * IDIM];
__device__ __align__(16) __half g_cat_h[BATCH * 1024];
__device__ __align__(16) __half g_decin_h[BATCH * 912];
__device__ __align__(16) __half g_hidden_h[BATCH * 1024];
__device__ __align__(16) float  g_gates[BATCH * 2048];
__device__ __align__(16) float  g_hbuf[BATCH * HDIM];
__device__ __align__(16) float  g_e[BATCH * ADIM];
__device__ __align__(16) float  g_att[BATCH * ADIM];
__device__ __align__(16) float  g_gen[BATCH];

// ---------------------------------------------------------------------------
// helpers
// ---------------------------------------------------------------------------
__device__ __forceinline__ float sigf(float x) { return 1.f / (1.f + __expf(-x)); }

__device__ __forceinline__ void mma_f16(float* c, const uint32_t* a, const uint32_t* b) {
    asm volatile(
        "mma.sync.aligned.m16n8k16.row.col.f32.f16.f16.f32 "
        "{%0,%1,%2,%3}, {%4,%5,%6,%7}, {%8,%9}, {%0,%1,%2,%3};\n"
        : "+f"(c[0]), "+f"(c[1]), "+f"(c[2]), "+f"(c[3])
        : "r"(a[0]), "r"(a[1]), "r"(a[2]), "r"(a[3]), "r"(b[0]), "r"(b[1]));
}

__device__ __forceinline__ void ldsm_x4(uint32_t* r, uint32_t addr) {
    asm volatile("ldmatrix.sync.aligned.m8n8.x4.shared.b16 {%0,%1,%2,%3}, [%4];"
                 : "=r"(r[0]), "=r"(r[1]), "=r"(r[2]), "=r"(r[3]) : "r"(addr));
}

// cp.async 16B with zero-fill predication (src-size 0 => 16 zero bytes)
__device__ __forceinline__ void cp16(uint32_t dst, const void* src, bool p) {
    int sz = p ? 16 : 0;
    asm volatile("cp.async.cg.shared.global [%0], [%1], 16, %2;\n"
                 :: "r"(dst), "l"(src), "r"(sz));
}
__device__ __forceinline__ void cp_commit() { asm volatile("cp.async.commit_group;\n" ::); }
__device__ __forceinline__ void cp_wait1()  { asm volatile("cp.async.wait_group 1;\n" ::); }
__device__ __forceinline__ void cp_wait0()  { asm volatile("cp.async.wait_group 0;\n" ::); }

// ---------------------------------------------------------------------------
// fp16 GEMM: C(256,N) = act( A(256,K)h @ W(N,K)h^T + b1 [+ b2] )
// BM=128 BN=128 BK=64(halves), 2-stage cp.async (32KB/stage, 64KB total ->
// 2 CTAs/SM). 256 thr, 8 warps (2x4), warp tile 64x32.
// smem rows = 128B (64 halves) with SW128 granule swizzle c^(row&7) ->
// conflict-free ldmatrix + stores. Fragments via ldmatrix.x4.
// Grid (2, NB): 2 m-blocks sharing a W tile adjacent -> co-resident -> W
// streamed from DRAM once. outh: store C as fp16 (feeds next GEMM).
// ---------------------------------------------------------------------------
#define HG_STAGE 32768
#define HG_SMEM  (2 * HG_STAGE)

__global__ __launch_bounds__(256, 2) void hgemm(
    const __half* __restrict__ A, const __half* __restrict__ W,
    const float* __restrict__ b1, const float* __restrict__ b2,
    void* __restrict__ Cv, int N, int K, int ldc, int act, int outh)
{
    extern __shared__ char smem[];
    uint32_t sb = (uint32_t)__cvta_generic_to_shared(smem);
    int tid = threadIdx.x, lane = tid & 31, warp = tid >> 5;
    int wm = warp >> 2, wn = warp & 3;
    int m0 = blockIdx.x * 128, n0 = blockIdx.y * 128;
    int NT = (K + 63) / 64;

    // ---- loader: threads 0-127 -> A row t; 128-255 -> B row t-128 ----
    int lrow = tid & 127;
    bool isB = tid >= 128;
    bool rowok;
    const __half* gptr;
    if (!isB) { gptr = A + (size_t)(m0 + lrow) * K; rowok = true; }
    else { int nr = n0 + lrow; rowok = nr < N; gptr = W + (size_t)(rowok ? nr : 0) * K; }
    uint32_t dbase = sb + (isB ? 16384u : 0u) + (uint32_t)lrow * 128u;
    int lrs = lrow & 7;

    auto load_stage = [&](int slot, int k0) {
        uint32_t d = dbase + slot * HG_STAGE;
        #pragma unroll
        for (int c = 0; c < 8; c++) {
            int k = k0 + c * 8;
            bool pk = rowok && (k + 8 <= K);
            cp16(d + (uint32_t)((c ^ lrs) << 4), gptr + k, pk);
        }
    };

    // ---- fragment address components ----
    int row_a = wm * 64 + (lane & 15);
    int ka = lane >> 4;             // k-half for A ldmatrix
    int rs_a = row_a & 7;
    int row_b = wn * 32 + ((lane >> 4) << 3) + (lane & 7);
    int kb = (lane >> 3) & 1;       // k-half for B ldmatrix
    int rs_b = lane & 7;

    float acc[4][4][4];
    #pragma unroll
    for (int i = 0; i < 4; i++)
        #pragma unroll
        for (int j = 0; j < 4; j++)
            #pragma unroll
            for (int q = 0; q < 4; q++) acc[i][j][q] = 0.f;

    load_stage(0, 0);  cp_commit();
    load_stage(1, 64); cp_commit();

    for (int kt = 0; kt < NT; kt++) {
        if (kt + 1 < NT) cp_wait1(); else cp_wait0();
        __syncthreads();

        uint32_t sA = sb + (kt & 1) * HG_STAGE;
        uint32_t sB = sA + 16384u;
        #pragma unroll
        for (int kk = 0; kk < 4; kk++) {
            uint32_t af[4][4], bf[4][2];
            uint32_t offA = (uint32_t)((((kk * 2 + ka) ^ rs_a) << 4));
            #pragma unroll
            for (int mt = 0; mt < 4; mt++)
                ldsm_x4(af[mt], sA + (uint32_t)((row_a + mt * 16) * 128) + offA);
            uint32_t offB = (uint32_t)((((kk * 2 + kb) ^ rs_b) << 4));
            #pragma unroll
            for (int p = 0; p < 2; p++) {
                uint32_t r[4];
                ldsm_x4(r, sB + (uint32_t)((row_b + p * 16) * 128) + offB);
                bf[2 * p][0] = r[0]; bf[2 * p][1] = r[1];
                bf[2 * p + 1][0] = r[2]; bf[2 * p + 1][1] = r[3];
            }
            #pragma unroll
            for (int mt = 0; mt < 4; mt++)
                #pragma unroll
                for (int nt = 0; nt < 4; nt++)
                    mma_f16(acc[mt][nt], af[mt], bf[nt]);
        }
        __syncthreads();
        int kn = kt + 2;
        if (kn < NT) { load_stage(kt & 1, kn * 64); cp_commit(); }
    }

    // ---- epilogue ----
    int gr = lane >> 2, gc = (lane & 3) * 2;
    #pragma unroll
    for (int mt = 0; mt < 4; mt++) {
        int row = m0 + wm * 64 + mt * 16 + gr;
        #pragma unroll
        for (int nt = 0; nt < 4; nt++) {
            int col = n0 + wn * 32 + nt * 8 + gc;
            if (col < N) {   // N even, col even -> col+1 < N too
                float bb0 = b1[col]     + (b2 ? b2[col]     : 0.f);
                float bb1 = b1[col + 1] + (b2 ? b2[col + 1] : 0.f);
                float v00 = acc[mt][nt][0] + bb0, v01 = acc[mt][nt][1] + bb1;
                float v10 = acc[mt][nt][2] + bb0, v11 = acc[mt][nt][3] + bb1;
                if (act) { v00 = tanhf(v00); v01 = tanhf(v01);
                           v10 = tanhf(v10); v11 = tanhf(v11); }
                if (outh) {
                    __half* Ch = (__half*)Cv;
                    *(__half2*)&Ch[(size_t)row * ldc + col]       = __floats2half2_rn(v00, v01);
                    *(__half2*)&Ch[(size_t)(row + 8) * ldc + col] = __floats2half2_rn(v10, v11);
                } else {
                    float* C = (float*)Cv;
                    *(float2*)&C[(size_t)row * ldc + col]       = make_float2(v00, v01);
                    *(float2*)&C[(size_t)(row + 8) * ldc + col] = make_float2(v10, v11);
                }
            }
        }
    }
}

// ---------------------------------------------------------------------------
// fp32 -> fp16 converts
// ---------------------------------------------------------------------------
__global__ void f2h(const float* __restrict__ in, __half* __restrict__ out, int n)
{
    int i = (blockIdx.x * blockDim.x + threadIdx.x) * 8;
    if (i >= n) return;
    float4 a = *(const float4*)(in + i);
    float4 b = *(const float4*)(in + i + 4);
    __half2 h[4] = { __floats2half2_rn(a.x, a.y), __floats2half2_rn(a.z, a.w),
                     __floats2half2_rn(b.x, b.y), __floats2half2_rn(b.z, b.w) };
    *(uint4*)(out + i) = *(uint4*)h;
}

// wide variant: 16 elems/thread (64B LDG stream) for the 51.2M-elem fc2_w
__global__ __launch_bounds__(256) void f2h16(const float* __restrict__ in,
                                             __half* __restrict__ out, int n)
{
    int i = (blockIdx.x * blockDim.x + threadIdx.x) * 16;
    if (i >= n) return;
    float4 a = *(const float4*)(in + i);
    float4 b = *(const float4*)(in + i + 4);
    float4 c = *(const float4*)(in + i + 8);
    float4 d = *(const float4*)(in + i + 12);
    __half2 h0[4] = { __floats2half2_rn(a.x, a.y), __floats2half2_rn(a.z, a.w),
                      __floats2half2_rn(b.x, b.y), __floats2half2_rn(b.z, b.w) };
    __half2 h1[4] = { __floats2half2_rn(c.x, c.y), __floats2half2_rn(c.z, c.w),
                      __floats2half2_rn(d.x, d.y), __floats2half2_rn(d.z, d.w) };
    *(uint4*)(out + i)     = *(uint4*)h0;
    *(uint4*)(out + i + 8) = *(uint4*)h1;
}

// pack [Wh_w | Ws_w] -> catw_h (400 x 1024) fp16
__global__ void pack_catw(const float* __restrict__ Wh, const float* __restrict__ Ws,
                          __half* __restrict__ catw)
{
    int n = blockIdx.x, t = threadIdx.x;        // 400 blocks x 128 threads
    int j = t * 8;
    const float* src = (j < HDIM) ? (Wh + n * HDIM + j) : (Ws + n * HDIM + (j - HDIM));
    float4 a = *(const float4*)src;
    float4 b = *(const float4*)(src + 4);
    __half2 h[4] = { __floats2half2_rn(a.x, a.y), __floats2half2_rn(a.z, a.w),
                     __floats2half2_rn(b.x, b.y), __floats2half2_rn(b.z, b.w) };
    *(uint4*)(catw + n * 1024 + j) = *(uint4*)h;
}

// ---------------------------------------------------------------------------
// LSTM elementwise: h = sig(o)*tanh(sig(i)*tanh(g)); fills decin_h[:,400:]
// (fp16) and cat_h = [enc_state | h] (fp16); h kept fp32 for gen.
// ---------------------------------------------------------------------------
__global__ void lstm_h_kernel(const float* __restrict__ gates,
                              const float* __restrict__ es,
                              float* __restrict__ h, __half* __restrict__ decin_h,
                              __half* __restrict__ cat_h)
{
    int idx = blockIdx.x * blockDim.x + threadIdx.x;
    if (idx >= BATCH * HDIM) return;
    int b = idx >> 9, k = idx & 511;
    const float* g = gates + b * 2048;
    float ig = sigf(g[k]);
    float gg = tanhf(g[1024 + k]);
    float og = sigf(g[1536 + k]);
    float c = ig * gg;
    float hv = og * tanhf(c);
    h[idx] = hv;
    decin_h[b * 912 + 400 + k] = __float2half_rn(hv);
    cat_h[b * 1024 + k] = __float2half_rn(es[idx]);
    cat_h[b * 1024 + 512 + k] = __float2half_rn(hv);
}

// ---------------------------------------------------------------------------
// Fused: attention = v*softmax(e); context -> decin_h[:, :400] (fp16); gen[b]
// One block per batch row, 512 threads.
// ---------------------------------------------------------------------------
__global__ __launch_bounds__(512) void attn_context_gen(
    const float* __restrict__ e, const float* __restrict__ v,
    const float* __restrict__ enc, const float* __restrict__ h,
    const float* __restrict__ x,
    const float* __restrict__ pg1, const float* __restrict__ pg2,
    const float* __restrict__ pg3,
    float* __restrict__ att, __half* __restrict__ decin_h, float* __restrict__ gen)
{
    __shared__ float att_s[ADIM];
    __shared__ float red[512];
    int b = blockIdx.x, t = threadIdx.x;

    float ev = (t < ADIM) ? e[b * ADIM + t] : -1e30f;
    red[t] = ev; __syncthreads();
    for (int s = 256; s > 0; s >>= 1) { if (t < s) red[t] = fmaxf(red[t], red[t + s]); __syncthreads(); }
    float m = red[0]; __syncthreads();
    float ex = (t < ADIM) ? __expf(ev - m) : 0.f;
    red[t] = ex; __syncthreads();
    for (int s = 256; s > 0; s >>= 1) { if (t < s) red[t] += red[t + s]; __syncthreads(); }
    float inv = 1.f / red[0]; __syncthreads();

    float av = 0.f;
    if (t < ADIM) {
        av = v[t] * ex * inv;
        att_s[t] = av;
        att[b * ADIM + t] = av;
    }
    __syncthreads();

    float ctx = 0.f;
    if (t < ADIM) {
        const float* ep = enc + (size_t)b * (ADIM * ADIM) + t;
        float s0 = 0.f, s1 = 0.f, s2 = 0.f, s3 = 0.f;
        float s4 = 0.f, s5 = 0.f, s6 = 0.f, s7 = 0.f;
        #pragma unroll 2
        for (int a = 0; a < ADIM; a += 8) {
            s0 += att_s[a]     * ep[(a)     * ADIM];
            s1 += att_s[a + 1] * ep[(a + 1) * ADIM];
            s2 += att_s[a + 2] * ep[(a + 2) * ADIM];
            s3 += att_s[a + 3] * ep[(a + 3) * ADIM];
            s4 += att_s[a + 4] * ep[(a + 4) * ADIM];
            s5 += att_s[a + 5] * ep[(a + 5) * ADIM];
            s6 += att_s[a + 6] * ep[(a + 6) * ADIM];
            s7 += att_s[a + 7] * ep[(a + 7) * ADIM];
        }
        ctx = ((s0 + s1) + (s2 + s3)) + ((s4 + s5) + (s6 + s7));
        decin_h[b * 912 + t] = __float2half_rn(ctx);
    }

    float p = h[b * HDIM + t] * pg3[t];
    if (t < ADIM) p += ctx * pg2[t];
    if (t < IDIM) p += x[b * IDIM + t] * pg1[t];
    red[t] = p; __syncthreads();
    for (int s = 256; s > 0; s >>= 1) { if (t < s) red[t] += red[t + s]; __syncthreads(); }
    if (t == 0) gen[b] = sigf(red[0]);
}

// ---------------------------------------------------------------------------
// Per-row: online softmax over 50000 logits (in-place), *gen, zero OOV,
// scatter-add copy distribution. One block per row (row-local scatter).
// ---------------------------------------------------------------------------
__global__ __launch_bounds__(1024) void softmax_final(
    float* __restrict__ out, const float* __restrict__ gen,
    const float* __restrict__ att, const int* __restrict__ ids)
{
    __shared__ float shm[1024];
    __shared__ float shs[1024];
    int b = blockIdx.x, t = threadIdx.x;
    float* row = out + (size_t)b * OUTC;
    float2* row2 = (float2*)row;

    float m = -1e30f, s = 0.f;
    for (int i = t; i < VDIM / 2; i += 1024) {
        float2 vv = row2[i];
        float lm = fmaxf(vv.x, vv.y);
        float nm = fmaxf(m, lm);
        s = s * __expf(m - nm) + __expf(vv.x - nm) + __expf(vv.y - nm);
        m = nm;
    }
    shm[t] = m; shs[t] = s; __syncthreads();
    for (int st = 512; st > 0; st >>= 1) {
        if (t < st) {
            float m2 = shm[t + st], s2 = shs[t + st];
            float nm = fmaxf(shm[t], m2);
            shs[t] = shs[t] * __expf(shm[t] - nm) + s2 * __expf(m2 - nm);
            shm[t] = nm;
        }
        __syncthreads();
    }
    float M = shm[0];
    float g = gen[b];
    float inv = g / shs[0];

    for (int i = t; i < VDIM / 2; i += 1024) {
        float2 vv = row2[i];
        vv.x = __expf(vv.x - M) * inv;
        vv.y = __expf(vv.y - M) * inv;
        row2[i] = vv;
    }
    if (t < 50) row[VDIM + t] = 0.f;
    __syncthreads();

    float gc = 1.f - g;
    if (t < ADIM) atomicAdd(&row[ids[b * ADIM + t]], gc * att[b * ADIM + t]);
}

// ---------------------------------------------------------------------------
// launch
// ---------------------------------------------------------------------------
extern "C" void kernel_launch(void* const* d_in, const int* in_sizes, int n_in,
                              void* d_out, int out_size)
{
    int s = (n_in > 5 && in_sizes[5] == 1) ? 1 : 0;
    const float* x         = (const float*)d_in[0];
    const float* enc_out   = (const float*)d_in[2];
    const float* enc_state = (const float*)d_in[4];
    const int*   ids       = (const int*)  d_in[5 + s];
    const float* W_ih      = (const float*)d_in[6 + s];
    const float* b_ih      = (const float*)d_in[8 + s];
    const float* b_hh      = (const float*)d_in[9 + s];
    const float* Wh_w      = (const float*)d_in[10 + s];
    const float* Wh_b      = (const float*)d_in[11 + s];
    const float* Ws_w      = (const float*)d_in[12 + s];
    const float* Ws_b      = (const float*)d_in[13 + s];
    const float* v         = (const float*)d_in[14 + s];
    const float* fc1_w     = (const float*)d_in[15 + s];
    const float* fc1_b     = (const float*)d_in[16 + s];
    const float* fc2_w     = (const float*)d_in[17 + s];
    const float* fc2_b     = (const float*)d_in[18 + s];
    const float* pg1       = (const float*)d_in[19 + s];
    const float* pg2       = (const float*)d_in[20 + s];
    const float* pg3       = (const float*)d_in[21 + s];
    float* out = (float*)d_out;

    void *p_fc2w, *p_wih, *p_catw, *p_fc1w, *p_xh, *p_cat, *p_decin, *p_hid;
    void *p_gates, *p_h, *p_e, *p_att, *p_gen;
    cudaGetSymbolAddress(&p_fc2w, g_fc2w_h);
    cudaGetSymbolAddress(&p_wih, g_wih_h);
    cudaGetSymbolAddress(&p_catw, g_catw_h);
    cudaGetSymbolAddress(&p_fc1w, g_fc1w_h);
    cudaGetSymbolAddress(&p_xh, g_x_h);
    cudaGetSymbolAddress(&p_cat, g_cat_h);
    cudaGetSymbolAddress(&p_decin, g_decin_h);
    cudaGetSymbolAddress(&p_hid, g_hidden_h);
    cudaGetSymbolAddress(&p_gates, g_gates);
    cudaGetSymbolAddress(&p_h, g_hbuf);
    cudaGetSymbolAddress(&p_e, g_e);
    cudaGetSymbolAddress(&p_att, g_att);
    cudaGetSymbolAddress(&p_gen, g_gen);
    __half* fc2w_h = (__half*)p_fc2w;
    __half* wih_h  = (__half*)p_wih;
    __half* catw_h = (__half*)p_catw;
    __half* fc1w_h = (__half*)p_fc1w;
    __half* x_h    = (__half*)p_xh;
    __half* cat_h  = (__half*)p_cat;
    __half* decin_h= (__half*)p_decin;
    __half* hid_h  = (__half*)p_hid;
    float* gates   = (float*)p_gates;
    float* h       = (float*)p_h;
    float* e       = (float*)p_e;
    float* att     = (float*)p_att;
    float* gen     = (float*)p_gen;

    cudaFuncSetAttribute(hgemm, cudaFuncAttributeMaxDynamicSharedMemorySize, HG_SMEM);

    // One-time side stream + events (created on the first, uncaptured call;
    // reused under graph capture as fork/join edges). No device allocs.
    static cudaStream_t s_side = nullptr;
    static cudaEvent_t  ev_fork = nullptr, ev_join = nullptr;
    if (s_side == nullptr) {
        cudaStreamCreateWithFlags(&s_side, cudaStreamNonBlocking);
        cudaEventCreateWithFlags(&ev_fork, cudaEventDisableTiming);
        cudaEventCreateWithFlags(&ev_join, cudaEventDisableTiming);
    }

    // ---- fork: fc2_w convert (205MB stream) on side stream ----
    cudaEventRecord(ev_fork, 0);
    cudaStreamWaitEvent(s_side, ev_fork, 0);
    {
        int n = VDIM * 1024;                       // 51.2M elems
        f2h16<<<(n / 16 + 255) / 256, 256, 0, s_side>>>(fc2_w, fc2w_h, n);
    }
    cudaEventRecord(ev_join, s_side);

    // ---- main chain (independent of fc2 convert) ----
    f2h<<<(BATCH * IDIM / 8 + 255) / 256, 256>>>(x, x_h, BATCH * IDIM);
    f2h<<<(2048 * IDIM / 8 + 255) / 256, 256>>>(W_ih, wih_h, 2048 * IDIM);
    pack_catw<<<ADIM, 128>>>(Wh_w, Ws_w, catw_h);
    f2h<<<(1024 * 912 / 8 + 255) / 256, 256>>>(fc1_w, fc1w_h, 1024 * 912);

    // 1) gates = x0 @ W_ih^T + b_ih + b_hh        (256 x 2048, K=256)
    hgemm<<<dim3(2, 16), 256, HG_SMEM>>>(x_h, wih_h, b_ih, b_hh,
                                         gates, 2048, IDIM, 2048, 0, 0);
    // 2) h, decin[:,400:], cat=[es|h]
    lstm_h_kernel<<<512, 256>>>(gates, enc_state, h, decin_h, cat_h);
    // 3) e = tanh(cat @ catw^T + Wh_b + Ws_b)     (256 x 400, K=1024)
    hgemm<<<dim3(2, 4), 256, HG_SMEM>>>(cat_h, catw_h, Wh_b, Ws_b,
                                        e, ADIM, 1024, ADIM, 1, 0);
    // 4) attention softmax + context + gen (fused)
    attn_context_gen<<<256, 512>>>(e, v, enc_out, h, x, pg1, pg2, pg3,
                                   att, decin_h, gen);
    // 5) hidden = decin @ fc1_w^T + fc1_b         (256 x 1024, K=912) -> fp16
    hgemm<<<dim3(2, 8), 256, HG_SMEM>>>(decin_h, fc1w_h, fc1_b, nullptr,
                                        hid_h, 1024, 912, 1024, 0, 1);

    // ---- join: fc2 GEMM needs fc2w_h ----
    cudaStreamWaitEvent(0, ev_join, 0);

    // 6) logits -> out[:, :50000]                 (256 x 50000, K=1024)
    hgemm<<<dim3(2, 391), 256, HG_SMEM>>>(hid_h, fc2w_h, fc2_b, nullptr,
                                          out, VDIM, 1024, OUTC, 0, 0);
    // 7) softmax * gen, zero OOV, scatter-add copy distribution
    softmax_final<<<256, 1024>>>(out, gen, att, ids);

    (void)out_size; (void)n_in;
}